// round 2
// baseline (speedup 1.0000x reference)
#include <cuda_runtime.h>
#include <math.h>

#define BS 2
#define SN 512
#define W 64
#define MODES 16
#define PAIRS ((SN*(SN-1))/2)

// ---------------- scratch (device globals; no allocation) ----------------
__device__ float g_h  [BS*W*SN];     // (b,c,s)
__device__ float g_hT [BS*SN*W];     // (b,s,c)
__device__ float g_a  [BS*W*SN];
__device__ float g_aT [BS*SN*W];
__device__ float g_p  [BS*W*SN];
__device__ float g_pT [BS*SN*W];
__device__ float g_xr [BS*SN*SN];    // pairwise |x_i - x_j|
__device__ float g_vr [BS*SN*SN];    // pairwise |v_i - v_j|
__device__ float g_Xf [BS*W*MODES*2];
__device__ float g_Y  [BS*W*MODES*2];
__device__ int   g_vrmax[4*BS];      // float bits, per (layer,b)
__device__ float g_cos[SN*MODES];
__device__ float g_sin[SN*MODES];

// ---------------- init: trig tables + vrmax reset ----------------
__global__ void k_init() {
    int t = blockIdx.x * blockDim.x + threadIdx.x;
    if (t < SN * MODES) {
        int j = t / MODES, k = t % MODES;
        int ph = (j * k) & (SN - 1);            // exact mod-512 reduction
        double ang = (double)ph * (6.283185307179586476925286766559 / (double)SN);
        g_cos[t] = (float)cos(ang);
        g_sin[t] = (float)sin(ang);
    }
    if (t < 4 * BS) g_vrmax[t] = 0;
}

// ---------------- fc0 + transpose: h[b,c,s] ----------------
__global__ void k_fc0(const float* __restrict__ x, const float* __restrict__ w,
                      const float* __restrict__ b) {
    int bb = blockIdx.x, c = blockIdx.y, j = threadIdx.x;
    float x0 = x[(bb*SN + j)*2 + 0];
    float x1 = x[(bb*SN + j)*2 + 1];
    g_h[(bb*W + c)*SN + j] = x0 * w[c] + x1 * w[W + c] + b[c];
}

// ---------------- forward DFT, modes 0..15 (unnormalized) ----------------
__global__ void k_dft() {
    __shared__ float sh[SN];
    int bc = blockIdx.x;
    int t = threadIdx.x;
    sh[t] = g_h[bc*SN + t];
    __syncthreads();
    int wp = t >> 5, lane = t & 31;           // 16 warps = 16 modes
    float re = 0.f, im = 0.f;
    for (int j = lane; j < SN; j += 32) {
        float hv = sh[j];
        re += hv * g_cos[j*MODES + wp];
        im -= hv * g_sin[j*MODES + wp];
    }
    #pragma unroll
    for (int o = 16; o; o >>= 1) {
        re += __shfl_down_sync(0xffffffffu, re, o);
        im += __shfl_down_sync(0xffffffffu, im, o);
    }
    if (lane == 0) {
        g_Xf[(bc*MODES + wp)*2 + 0] = re;
        g_Xf[(bc*MODES + wp)*2 + 1] = im;
    }
}

// ---------------- per-mode channel mix: Y[b,o,k] = sum_i Xf[b,i,k]*W[i,o,k] ----
__global__ void k_mix(const float* __restrict__ specw, int layer) {
    int b = blockIdx.x, k = blockIdx.y, o = threadIdx.x;
    const float* wl = specw + (size_t)layer * W * W * MODES * 2;
    float yre = 0.f, yim = 0.f;
    for (int i = 0; i < W; i++) {
        float xr = g_Xf[((b*W + i)*MODES + k)*2 + 0];
        float xi = g_Xf[((b*W + i)*MODES + k)*2 + 1];
        float wr = wl[((i*W + o)*MODES + k)*2 + 0];
        float wi = wl[((i*W + o)*MODES + k)*2 + 1];
        yre += xr*wr - xi*wi;
        yim += xr*wi + xi*wr;
    }
    g_Y[((b*W + o)*MODES + k)*2 + 0] = yre;
    g_Y[((b*W + o)*MODES + k)*2 + 1] = yim;
}

// ---------------- inverse synth (c2r, imag of mode-0 ignored), 1/n total ----
__global__ void k_synth() {
    __shared__ float sy[MODES*2];
    int b = blockIdx.x, o = blockIdx.y, j = threadIdx.x;
    if (j < MODES*2) sy[j] = g_Y[((b*W + o)*MODES)*2 + j];
    __syncthreads();
    float acc = sy[0];
    #pragma unroll
    for (int k = 1; k < MODES; k++)
        acc += 2.f * (sy[2*k] * g_cos[j*MODES + k] - sy[2*k+1] * g_sin[j*MODES + k]);
    float a = acc * (1.0f / (float)SN);
    g_a [(b*W + o)*SN + j] = a;
    g_aT[(b*SN + j)*W + o] = a;
}

// ---------------- 1x1 conv: p[b,o,j] = sum_c w[o,c] h[b,c,j] + b[o] --------
__global__ void k_conv(const float* __restrict__ cw, const float* __restrict__ cb,
                       int layer) {
    __shared__ float sw[W];
    int b = blockIdx.x, o = blockIdx.y, j = threadIdx.x;
    if (threadIdx.x < W) sw[threadIdx.x] = cw[((size_t)layer*W + o)*W + threadIdx.x];
    __syncthreads();
    float acc = cb[layer*W + o];
    for (int c = 0; c < W; c++)
        acc += sw[c] * g_h[(b*W + c)*SN + j];
    g_p [(b*W + o)*SN + j] = acc;
    g_pT[(b*SN + j)*W + o] = acc;
}

// ---------------- pairwise distances + vrmax ----------------
__global__ void k_pair(int layer) {
    __shared__ float pI[W][32], pJ[W][32], aI[W][32], aJ[W][32];
    __shared__ int smax;
    int b = blockIdx.x, I0 = blockIdx.y * 32, J0 = blockIdx.z * 32;
    int t = threadIdx.y * 32 + threadIdx.x;
    if (t == 0) smax = 0;
    for (int e = t; e < W * 32; e += 1024) {
        int c = e >> 5, col = e & 31;
        pI[c][col] = g_p[(b*W + c)*SN + I0 + col];
        pJ[c][col] = g_p[(b*W + c)*SN + J0 + col];
        aI[c][col] = g_a[(b*W + c)*SN + I0 + col];
        aJ[c][col] = g_a[(b*W + c)*SN + J0 + col];
    }
    __syncthreads();
    int il = threadIdx.y, jl = threadIdx.x;
    float sx = 0.f, sv = 0.f;
    #pragma unroll 8
    for (int c = 0; c < W; c++) {
        float dx = pI[c][il] - pJ[c][jl]; sx += dx * dx;
        float dv = aI[c][il] - aJ[c][jl]; sv += dv * dv;
    }
    float xr = sqrtf(sx), vr = sqrtf(sv);
    g_xr[((size_t)b*SN + I0 + il)*SN + J0 + jl] = xr;
    g_vr[((size_t)b*SN + I0 + il)*SN + J0 + jl] = vr;
    // block-level max(vr) -> global atomic (positive floats compare as ints)
    float m = vr;
    #pragma unroll
    for (int o = 16; o; o >>= 1) m = fmaxf(m, __shfl_down_sync(0xffffffffu, m, o));
    if (jl == 0) atomicMax(&smax, __float_as_int(m));
    __syncthreads();
    if (t == 0) atomicMax(&g_vrmax[layer*BS + b], smax);
}

// ---------------- DSMC collide: per (b, j) column update ----------------
__global__ void k_collide(const float* __restrict__ vecs, int layer, int relu) {
    __shared__ int   s_idx[SN];
    __shared__ int   s_pid[SN];
    __shared__ float s_wt [SN];
    __shared__ int   cnt, wcnt[8], wbase[8];
    __shared__ float sMx[256], sMv[256], sR[256];

    int b = blockIdx.x, j = (int)blockIdx.y;
    int tid = threadIdx.x, lane = tid & 31, wp = tid >> 5;
    if (tid == 0) cnt = 0;
    float vrmax = __int_as_float(g_vrmax[layer*BS + b]);
    float inv = 1.0f / vrmax;
    const float* vrrow = g_vr + ((size_t)b*SN + j)*SN;
    const float* xrrow = g_xr + ((size_t)b*SN + j)*SN;
    __syncthreads();

    // deterministic compaction of collision partners (ordered by i)
    for (int base = 0; base < SN; base += 256) {
        int i = base + tid;
        float vr = vrrow[i];
        float ux = expf(-xrrow[i]);
        bool pred = (vr * inv * ux) > 0.1f;
        unsigned m = __ballot_sync(0xffffffffu, pred);
        if (lane == 0) wcnt[wp] = __popc(m);
        __syncthreads();
        if (tid == 0) {
            int s0 = cnt;
            for (int q = 0; q < 8; q++) { wbase[q] = s0; s0 += wcnt[q]; }
            cnt = s0;
        }
        __syncthreads();
        if (pred) {
            int pos = wbase[wp] + __popc(m & ((1u << lane) - 1u));
            int lo = i < j ? i : j, hi = i < j ? j : i;
            s_idx[pos] = i;
            s_pid[pos] = lo*SN - (lo*(lo+1))/2 + hi - lo - 1;
            s_wt [pos] = (i < j) ? vr : -vr;
        }
        __syncthreads();
    }

    int n = cnt;
    float mx = 0.f, mv = 0.f, rr = 0.f;
    int c = tid & 63, g = tid >> 6;      // 4 groups x 64 channels
    if (n > 0) {
        const float* vb = vecs + (((size_t)layer*BS + b)*W + c) * (size_t)PAIRS;
        for (int k = g; k < n; k += 4) {
            int i = s_idx[k];
            mx += g_pT[((size_t)b*SN + i)*W + c];
            mv += g_aT[((size_t)b*SN + i)*W + c];
            rr += s_wt[k] * vb[s_pid[k]];
        }
    }
    sMx[tid] = mx; sMv[tid] = mv; sR[tid] = rr;
    __syncthreads();

    if (tid < W) {
        float Mx = sMx[tid] + sMx[tid+64] + sMx[tid+128] + sMx[tid+192];
        float Mv = sMv[tid] + sMv[tid+64] + sMv[tid+128] + sMv[tid+192];
        float R  = sR [tid] + sR [tid+64] + sR [tid+128] + sR [tid+192];
        float Sc = (float)n;
        float aj = g_aT[((size_t)b*SN + j)*W + tid];
        float pj = g_pT[((size_t)b*SN + j)*W + tid];
        float vnew = aj + 0.5f*aj*Sc - 0.5f*Mv + R;
        float C = Sc + 1.0f;
        float xnew = (Mx + pj + pj*C) / (2.0f*C);
        float h = xnew + vnew;
        if (relu) h = fmaxf(h, 0.0f);
        g_h [(b*W + tid)*SN + j] = h;
        g_hT[((size_t)b*SN + j)*W + tid] = h;
    }
}

// ---------------- head: relu(h @ fc1 + b1) @ fc2 + b2 ----------------
__global__ void k_head(const float* __restrict__ w1, const float* __restrict__ b1,
                       const float* __restrict__ w2, const float* __restrict__ b2,
                       float* __restrict__ out) {
    __shared__ float sh[W];
    __shared__ float red[128];
    int b = blockIdx.x, s = blockIdx.y, m = threadIdx.x;
    if (m < W) sh[m] = g_hT[((size_t)b*SN + s)*W + m];
    __syncthreads();
    float acc = b1[m];
    for (int cc = 0; cc < W; cc++) acc += sh[cc] * w1[cc*128 + m];
    acc = fmaxf(acc, 0.0f) * w2[m];
    red[m] = acc;
    __syncthreads();
    #pragma unroll
    for (int o = 64; o; o >>= 1) { if (m < o) red[m] += red[m + o]; __syncthreads(); }
    if (m == 0) out[b*SN + s] = red[0] + b2[0];
}

// ---------------- launch ----------------
extern "C" void kernel_launch(void* const* d_in, const int* in_sizes, int n_in,
                              void* d_out, int out_size) {
    const float* x      = (const float*)d_in[0];
    // d_in[1] = v, unused by the reference computation
    const float* vecs   = (const float*)d_in[2];
    const float* fc0_w  = (const float*)d_in[3];
    const float* fc0_b  = (const float*)d_in[4];
    const float* spec_w = (const float*)d_in[5];
    const float* conv_w = (const float*)d_in[6];
    const float* conv_b = (const float*)d_in[7];
    const float* fc1_w  = (const float*)d_in[8];
    const float* fc1_b  = (const float*)d_in[9];
    const float* fc2_w  = (const float*)d_in[10];
    const float* fc2_b  = (const float*)d_in[11];
    float* out = (float*)d_out;

    k_init<<<16, 512>>>();
    k_fc0<<<dim3(BS, W), SN>>>(x, fc0_w, fc0_b);
    for (int l = 0; l < 4; l++) {
        k_dft  <<<BS*W, SN>>>();
        k_mix  <<<dim3(BS, MODES), W>>>(spec_w, l);
        k_synth<<<dim3(BS, W), SN>>>();
        k_conv <<<dim3(BS, W), SN>>>(conv_w, conv_b, l);
        k_pair <<<dim3(BS, 16, 16), dim3(32, 32)>>>(l);
        k_collide<<<dim3(BS, SN), 256>>>(vecs, l, (l < 3) ? 1 : 0);
    }
    k_head<<<dim3(BS, SN), 128>>>(fc1_w, fc1_b, fc2_w, fc2_b, out);
}

// round 3
// speedup vs baseline: 1.2390x; 1.2390x over previous
#include <cuda_runtime.h>
#include <math.h>

#define BS 2
#define SN 512
#define W 64
#define MODES 16
#define PAIRS ((SN*(SN-1))/2)
#define GRID 296
#define NTHR 256

// ---------------- scratch (device globals; no allocation) ----------------
__device__ float g_h [BS*W*SN];
__device__ float g_hT[BS*SN*W];
__device__ float g_a [BS*W*SN];
__device__ float g_aT[BS*SN*W];
__device__ float g_p [BS*W*SN];
__device__ float g_pT[BS*SN*W];
__device__ float g_xr[BS*SN*SN];
__device__ float g_vr[BS*SN*SN];
__device__ float g_Xf[BS*W*MODES*2];
__device__ int   g_vrmax[4*BS];
__device__ float g_cos[SN*MODES];
__device__ float g_sin[SN*MODES];

// ---------------- grid-wide barrier ----------------
__device__ int          g_count = 0;
__device__ volatile int g_gen   = 0;

__device__ __forceinline__ void gbar() {
    __syncthreads();
    if (threadIdx.x == 0) {
        __threadfence();
        int my = g_gen;
        if (atomicAdd(&g_count, 1) == GRID - 1) {
            g_count = 0;
            __threadfence();
            g_gen = my + 1;
        } else {
            while (g_gen == my) { }
        }
        __threadfence();
    }
    __syncthreads();
}

extern "C" __global__ void __launch_bounds__(NTHR, 2)
mega(const float* __restrict__ x, const float* __restrict__ vecs,
     const float* __restrict__ fc0_w, const float* __restrict__ fc0_b,
     const float* __restrict__ spec_w, const float* __restrict__ conv_w,
     const float* __restrict__ conv_b, const float* __restrict__ fc1_w,
     const float* __restrict__ fc1_b, const float* __restrict__ fc2_w,
     const float* __restrict__ fc2_b, float* __restrict__ out)
{
    __shared__ __align__(16) float sb[8448];   // 33 KB, aliased per phase
    const int tid  = threadIdx.x;
    const int lane = tid & 31;
    const int wp   = tid >> 5;

    // ================= phase 0: trig tables, vrmax reset, fc0 =================
    for (int t = blockIdx.x*NTHR + tid; t < SN*MODES; t += GRID*NTHR) {
        int j = t >> 4, k = t & 15;
        int ph = (j * k) & (SN - 1);
        double ang = (double)ph * (6.283185307179586476925286766559 / (double)SN);
        g_cos[t] = (float)cos(ang);
        g_sin[t] = (float)sin(ang);
    }
    for (int t = blockIdx.x*NTHR + tid; t < 4*BS; t += GRID*NTHR) g_vrmax[t] = 0;
    for (int e = blockIdx.x*NTHR + tid; e < BS*W*SN; e += GRID*NTHR) {
        int bb = e / (W*SN);
        int r  = e - bb*(W*SN);
        int c  = r >> 9;
        int j  = r & (SN-1);
        float x0 = x[(bb*SN + j)*2 + 0];
        float x1 = x[(bb*SN + j)*2 + 1];
        g_h[e] = x0*fc0_w[c] + x1*fc0_w[W + c] + fc0_b[c];
    }
    gbar();

    for (int l = 0; l < 4; l++) {
        // ============ Phase A: DFT (tasks 0..127) + 1x1 conv (128..255) ============
        for (int task = blockIdx.x; task < 256; task += GRID) {
            if (task < 128) {
                int bc = task;
                for (int e = tid; e < SN; e += NTHR) sb[e] = g_h[bc*SN + e];
                __syncthreads();
                int m0 = wp, m1 = wp + 8;
                float re0=0.f, im0=0.f, re1=0.f, im1=0.f;
                for (int j = lane; j < SN; j += 32) {
                    float hv = sb[j];
                    re0 += hv * g_cos[j*MODES + m0]; im0 -= hv * g_sin[j*MODES + m0];
                    re1 += hv * g_cos[j*MODES + m1]; im1 -= hv * g_sin[j*MODES + m1];
                }
                #pragma unroll
                for (int o = 16; o; o >>= 1) {
                    re0 += __shfl_down_sync(0xffffffffu, re0, o);
                    im0 += __shfl_down_sync(0xffffffffu, im0, o);
                    re1 += __shfl_down_sync(0xffffffffu, re1, o);
                    im1 += __shfl_down_sync(0xffffffffu, im1, o);
                }
                if (lane == 0) {
                    g_Xf[(bc*MODES + m0)*2 + 0] = re0;
                    g_Xf[(bc*MODES + m0)*2 + 1] = im0;
                    g_Xf[(bc*MODES + m1)*2 + 0] = re1;
                    g_Xf[(bc*MODES + m1)*2 + 1] = im1;
                }
                __syncthreads();
            } else {
                int t2 = task - 128;
                int b = t2 >> 6, o = t2 & 63;
                if (tid < W) sb[tid] = conv_w[((size_t)l*W + o)*W + tid];
                __syncthreads();
                float bias = conv_b[l*W + o];
                for (int j = tid; j < SN; j += NTHR) {
                    float acc = bias;
                    #pragma unroll 16
                    for (int c = 0; c < W; c++) acc += sb[c] * g_h[(b*W + c)*SN + j];
                    g_p [(b*W + o)*SN + j] = acc;
                    g_pT[((size_t)b*SN + j)*W + o] = acc;
                }
                __syncthreads();
            }
        }
        gbar();

        // ============ Phase B: mode-mix fused with inverse synth (tasks (b,o)=128) ============
        {
            const float2* wl2 = (const float2*)(spec_w + (size_t)l*W*W*MODES*2);
            for (int task = blockIdx.x; task < 128; task += GRID) {
                int b = task >> 6, o = task & 63;
                for (int e = tid; e < W*MODES*2; e += NTHR) sb[e] = g_Xf[b*W*MODES*2 + e];
                __syncthreads();
                int k0 = wp, k1 = wp + 8;
                float yr0=0.f, yi0=0.f, yr1=0.f, yi1=0.f;
                for (int i = lane; i < W; i += 32) {
                    float2 w0 = wl2[(i*W + o)*MODES + k0];
                    float2 w1 = wl2[(i*W + o)*MODES + k1];
                    float xr0 = sb[(i*MODES + k0)*2], xi0 = sb[(i*MODES + k0)*2 + 1];
                    float xr1 = sb[(i*MODES + k1)*2], xi1 = sb[(i*MODES + k1)*2 + 1];
                    yr0 += xr0*w0.x - xi0*w0.y;  yi0 += xr0*w0.y + xi0*w0.x;
                    yr1 += xr1*w1.x - xi1*w1.y;  yi1 += xr1*w1.y + xi1*w1.x;
                }
                #pragma unroll
                for (int o2 = 16; o2; o2 >>= 1) {
                    yr0 += __shfl_down_sync(0xffffffffu, yr0, o2);
                    yi0 += __shfl_down_sync(0xffffffffu, yi0, o2);
                    yr1 += __shfl_down_sync(0xffffffffu, yr1, o2);
                    yi1 += __shfl_down_sync(0xffffffffu, yi1, o2);
                }
                if (lane == 0) {
                    sb[2048 + k0*2] = yr0; sb[2048 + k0*2 + 1] = yi0;
                    sb[2048 + k1*2] = yr1; sb[2048 + k1*2 + 1] = yi1;
                }
                __syncthreads();
                for (int j = tid; j < SN; j += NTHR) {
                    float acc = sb[2048];
                    #pragma unroll
                    for (int k = 1; k < MODES; k++)
                        acc += 2.f*(sb[2048 + 2*k]*g_cos[j*MODES + k]
                                  - sb[2048 + 2*k + 1]*g_sin[j*MODES + k]);
                    float a = acc * (1.0f/(float)SN);
                    g_a [(b*W + o)*SN + j] = a;
                    g_aT[((size_t)b*SN + j)*W + o] = a;
                }
                __syncthreads();
            }
        }
        gbar();

        // ============ Phase C: pairwise distances (512 tile tasks) ============
        {
            float* pI = sb;        float* pJ = sb + 2048;
            float* aI = sb + 4096; float* aJ = sb + 6144;
            int* smax = (int*)(sb + 8192);
            for (int task = blockIdx.x; task < 512; task += GRID) {
                int b  = task >> 8;
                int rr = task & 255;
                int I0 = (rr >> 4) << 5, J0 = (rr & 15) << 5;
                __syncthreads();
                if (tid == 0) *smax = 0;
                for (int e = tid; e < W*32; e += NTHR) {
                    int c = e >> 5, col = e & 31;
                    pI[e] = g_p[(b*W + c)*SN + I0 + col];
                    pJ[e] = g_p[(b*W + c)*SN + J0 + col];
                    aI[e] = g_a[(b*W + c)*SN + I0 + col];
                    aJ[e] = g_a[(b*W + c)*SN + J0 + col];
                }
                __syncthreads();
                int tx = tid & 31, ty = tid >> 5;
                float sx[4] = {0,0,0,0}, sv[4] = {0,0,0,0};
                #pragma unroll 8
                for (int c = 0; c < W; c++) {
                    float pj = pJ[c*32 + tx], aj = aJ[c*32 + tx];
                    #pragma unroll
                    for (int r = 0; r < 4; r++) {
                        float dx = pI[c*32 + ty + 8*r] - pj; sx[r] += dx*dx;
                        float dv = aI[c*32 + ty + 8*r] - aj; sv[r] += dv*dv;
                    }
                }
                float vmax = 0.f;
                #pragma unroll
                for (int r = 0; r < 4; r++) {
                    int il = ty + 8*r;
                    float xr = sqrtf(sx[r]), vr = sqrtf(sv[r]);
                    g_xr[((size_t)b*SN + I0 + il)*SN + J0 + tx] = xr;
                    g_vr[((size_t)b*SN + I0 + il)*SN + J0 + tx] = vr;
                    vmax = fmaxf(vmax, vr);
                }
                #pragma unroll
                for (int o2 = 16; o2; o2 >>= 1)
                    vmax = fmaxf(vmax, __shfl_down_sync(0xffffffffu, vmax, o2));
                if (lane == 0) atomicMax(smax, __float_as_int(vmax));
                __syncthreads();
                if (tid == 0) atomicMax(&g_vrmax[l*BS + b], *smax);
            }
        }
        gbar();

        // ============ Phase D: DSMC collide (1024 column tasks) ============
        {
            int*   s_idx = (int*)sb;
            int*   s_pid = (int*)sb + 512;
            float* s_wt  = sb + 1024;
            float* sMx   = sb + 1536;
            float* sMv   = sb + 1792;
            float* sR    = sb + 2048;
            int*   ctl   = (int*)(sb + 2304);   // [0]=cnt [1..8]=wcnt [9..16]=wbase
            int relu = (l < 3);
            for (int task = blockIdx.x; task < BS*SN; task += GRID) {
                int b = task >> 9, j = task & 511;
                __syncthreads();
                if (tid == 0) ctl[0] = 0;
                float vrmax = __int_as_float(g_vrmax[l*BS + b]);
                float inv = 1.0f / vrmax;
                const float* vrrow = g_vr + ((size_t)b*SN + j)*SN;
                const float* xrrow = g_xr + ((size_t)b*SN + j)*SN;
                __syncthreads();

                for (int base = 0; base < SN; base += NTHR) {
                    int i = base + tid;
                    float vr = vrrow[i];
                    float ux = expf(-xrrow[i]);
                    bool pred = (vr * inv * ux) > 0.1f;
                    unsigned m = __ballot_sync(0xffffffffu, pred);
                    if (lane == 0) ctl[1 + wp] = __popc(m);
                    __syncthreads();
                    if (tid == 0) {
                        int s0 = ctl[0];
                        #pragma unroll
                        for (int q = 0; q < 8; q++) { ctl[9+q] = s0; s0 += ctl[1+q]; }
                        ctl[0] = s0;
                    }
                    __syncthreads();
                    if (pred) {
                        int pos = ctl[9 + wp] + __popc(m & ((1u << lane) - 1u));
                        int lo = i < j ? i : j, hi = i < j ? j : i;
                        s_idx[pos] = i;
                        s_pid[pos] = lo*SN - (lo*(lo+1))/2 + hi - lo - 1;
                        s_wt [pos] = (i < j) ? vr : -vr;
                    }
                    __syncthreads();
                }

                int n = ctl[0];
                float mx = 0.f, mv = 0.f, rr2 = 0.f;
                int c = tid & 63, g = tid >> 6;
                if (n > 0) {
                    const float* vb = vecs + (((size_t)l*BS + b)*W + c)*(size_t)PAIRS;
                    for (int k = g; k < n; k += 4) {
                        int i = s_idx[k];
                        mx  += g_pT[((size_t)b*SN + i)*W + c];
                        mv  += g_aT[((size_t)b*SN + i)*W + c];
                        rr2 += s_wt[k] * vb[s_pid[k]];
                    }
                }
                sMx[tid] = mx; sMv[tid] = mv; sR[tid] = rr2;
                __syncthreads();
                if (tid < W) {
                    float Mx = sMx[tid] + sMx[tid+64] + sMx[tid+128] + sMx[tid+192];
                    float Mv = sMv[tid] + sMv[tid+64] + sMv[tid+128] + sMv[tid+192];
                    float R  = sR [tid] + sR [tid+64] + sR [tid+128] + sR [tid+192];
                    float Sc = (float)n;
                    float aj = g_aT[((size_t)b*SN + j)*W + tid];
                    float pj = g_pT[((size_t)b*SN + j)*W + tid];
                    float vnew = aj + 0.5f*aj*Sc - 0.5f*Mv + R;
                    float C = Sc + 1.0f;
                    float xnew = (Mx + pj + pj*C) / (2.0f*C);
                    float h = xnew + vnew;
                    if (relu) h = fmaxf(h, 0.0f);
                    g_h [(b*W + tid)*SN + j] = h;
                    g_hT[((size_t)b*SN + j)*W + tid] = h;
                }
                __syncthreads();
            }
        }
        gbar();
    }

    // ================= head: relu(h@fc1+b1)@fc2+b2, 2 rows per task =================
    for (int task = blockIdx.x; task < 512; task += GRID) {
        int b = task >> 8, sp = task & 255;
        int half = tid >> 7, m = tid & 127;
        int s = sp*2 + half;
        __syncthreads();
        if (tid < 128) {
            int hh = tid >> 6, i = tid & 63;
            sb[tid] = g_hT[((size_t)b*SN + (sp*2 + hh))*W + i];
        }
        __syncthreads();
        float acc = fc1_b[m];
        #pragma unroll 16
        for (int cc = 0; cc < W; cc++) acc += sb[half*64 + cc] * fc1_w[cc*128 + m];
        acc = fmaxf(acc, 0.0f) * fc2_w[m];
        sb[128 + tid] = acc;
        __syncthreads();
        #pragma unroll
        for (int o2 = 64; o2; o2 >>= 1) {
            if (m < o2) sb[128 + half*128 + m] += sb[128 + half*128 + m + o2];
            __syncthreads();
        }
        if (m == 0) out[b*SN + s] = sb[128 + half*128] + fc2_b[0];
    }
}

// ---------------- launch ----------------
extern "C" void kernel_launch(void* const* d_in, const int* in_sizes, int n_in,
                              void* d_out, int out_size) {
    const float* x      = (const float*)d_in[0];
    const float* vecs   = (const float*)d_in[2];
    const float* fc0_w  = (const float*)d_in[3];
    const float* fc0_b  = (const float*)d_in[4];
    const float* spec_w = (const float*)d_in[5];
    const float* conv_w = (const float*)d_in[6];
    const float* conv_b = (const float*)d_in[7];
    const float* fc1_w  = (const float*)d_in[8];
    const float* fc1_b  = (const float*)d_in[9];
    const float* fc2_w  = (const float*)d_in[10];
    const float* fc2_b  = (const float*)d_in[11];
    float* out = (float*)d_out;

    mega<<<GRID, NTHR>>>(x, vecs, fc0_w, fc0_b, spec_w, conv_w, conv_b,
                         fc1_w, fc1_b, fc2_w, fc2_b, out);
}